// round 6
// baseline (speedup 1.0000x reference)
#include <cuda_runtime.h>
#include <cuda_bf16.h>
#include <math.h>
#include <stdint.h>

constexpr int Bb = 4;
constexpr int Np = 20000;
constexpr int Cc = 256;
constexpr int NS = 1024;
constexpr int NV = 300;

// output offsets (float32 elements), reference return order, row-major flatten
constexpr size_t OFF0 = 0;        // objectness (B,2,N)
constexpr size_t OFF1 = 160000;   // graspness (B,N)
constexpr size_t OFF2 = 240000;   // graspable_xyz (B,NS,3)
constexpr size_t OFF3 = 252288;   // graspable_inds (B,NS)
constexpr size_t OFF4 = 256384;   // graspable_features (B,C,NS)
constexpr size_t OFF5 = 1304960;  // fp2_graspness (B,NS)
constexpr size_t OFF6 = 1309056;  // vp_xyz (B,NS,3)
constexpr size_t OFF7 = 1321344;  // top_view_inds (B,NS)
constexpr size_t OFF8 = 1325440;  // vp_rot (B,NS,3,3)

__device__ unsigned char g_mask[Bb * Np];
__device__ int    g_cidx[Bb][Np];
__device__ float4 g_cxyz[Bb][Np];
__device__ int    g_sel[Bb][NS];

// ---------- f32x2 helpers (bitwise-identical to two scalar FFMAs) ----------
__device__ __forceinline__ unsigned long long pk2(float a, float b) {
    unsigned long long r;
    asm("mov.b64 %0, {%1, %2};" : "=l"(r) : "f"(a), "f"(b));
    return r;
}
__device__ __forceinline__ void up2(unsigned long long v, float& a, float& b) {
    asm("mov.b64 {%0, %1}, %2;" : "=f"(a), "=f"(b) : "l"(v));
}
__device__ __forceinline__ unsigned long long fma2(unsigned long long a, unsigned long long b,
                                                   unsigned long long c) {
    unsigned long long d;
    asm("fma.rn.f32x2 %0, %1, %2, %3;" : "=l"(d) : "l"(a), "l"(b), "l"(c));
    return d;
}

// ---------- shared GEMM tile constants (64 points x 256 co per block) ----------
constexpr int TPTS = 64;
constexpr int SM_FSM = 0;        // 256 x 64 = 16384
constexpr int SM_WSM = 16384;    // 8 x 256  = 2048
constexpr int SM_W2  = 18432;    // 768
constexpr int SM_B2  = 19200;    // 4
constexpr int SM1_FLOATS = 19204;
constexpr int SM_VSM = 19204;    // 900
constexpr int SM_IDX = 20104;    // 64 ints
constexpr int SM_VPS = 20168;    // 192
constexpr int SM4_FLOATS = 20360;

// tx=tid&7 owns pts 8tx..8tx+7, ty=tid>>3 owns co 8ty..8ty+7. Output acc[8][8] fp32.
__device__ __forceinline__ void gemm_tile(const float* __restrict__ W, float* sm,
                                          int tid, int tx, int ty, float acc[8][8]) {
    float* fsm = sm + SM_FSM;
    float* wsm = sm + SM_WSM;
    unsigned long long acc2[8][4];
#pragma unroll
    for (int j = 0; j < 8; ++j)
#pragma unroll
        for (int q = 0; q < 4; ++q) acc2[j][q] = 0ull;

    for (int ck = 0; ck < 32; ++ck) {
        {
            const float4* srcw = reinterpret_cast<const float4*>(W + tid * 256 + ck * 8);
            float4 a = srcw[0], b = srcw[1];
            wsm[0 * 256 + tid] = a.x; wsm[1 * 256 + tid] = a.y;
            wsm[2 * 256 + tid] = a.z; wsm[3 * 256 + tid] = a.w;
            wsm[4 * 256 + tid] = b.x; wsm[5 * 256 + tid] = b.y;
            wsm[6 * 256 + tid] = b.z; wsm[7 * 256 + tid] = b.w;
        }
        __syncthreads();
#pragma unroll
        for (int ci = 0; ci < 8; ++ci) {
            const float* wrow = wsm + ci * 256 + 8 * ty;
            float4 wa = *reinterpret_cast<const float4*>(wrow);
            float4 wb = *reinterpret_cast<const float4*>(wrow + 4);
            const float* frow = fsm + (ck * 8 + ci) * TPTS + 8 * tx;
            float4 fa = *reinterpret_cast<const float4*>(frow);
            float4 fb = *reinterpret_cast<const float4*>(frow + 4);
            unsigned long long f2[4] = {pk2(fa.x, fa.y), pk2(fa.z, fa.w),
                                        pk2(fb.x, fb.y), pk2(fb.z, fb.w)};
            float w[8] = {wa.x, wa.y, wa.z, wa.w, wb.x, wb.y, wb.z, wb.w};
#pragma unroll
            for (int j = 0; j < 8; ++j) {
                unsigned long long wd = pk2(w[j], w[j]);
#pragma unroll
                for (int q = 0; q < 4; ++q) acc2[j][q] = fma2(f2[q], wd, acc2[j][q]);
            }
        }
        __syncthreads();
    }
#pragma unroll
    for (int j = 0; j < 8; ++j)
#pragma unroll
        for (int q = 0; q < 4; ++q) up2(acc2[j][q], acc[j][2 * q], acc[j][2 * q + 1]);
}

__device__ __forceinline__ void bn_params(const float* gg, const float* be, const float* mm,
                                          const float* vv, const float* b1, int ty,
                                          float sc[8], float bias2[8], float b1v[8]) {
#pragma unroll
    for (int j = 0; j < 8; ++j) {
        int co = 8 * ty + j;
        float s = __fdiv_rn(gg[co], sqrtf(__fadd_rn(vv[co], 1e-5f)));
        sc[j] = s;
        bias2[j] = __fsub_rn(be[co], __fmul_rn(mm[co], s));
        b1v[j] = b1[co];
    }
}

__device__ __forceinline__ void head3(const float* w2sm, float acc[8][8],
                                      const float sc[8], const float bias2[8],
                                      const float b1v[8], int ty, float p3[3][8]) {
#pragma unroll
    for (int j = 0; j < 8; ++j) {
        int co = 8 * ty + j;
        float w0 = w2sm[co], w1c = w2sm[256 + co], w2c = w2sm[512 + co];
#pragma unroll
        for (int p = 0; p < 8; ++p) {
            float t = __fadd_rn(acc[j][p], b1v[j]);
            t = __fmul_rn(t, sc[j]);
            t = __fadd_rn(t, bias2[j]);
            float h = fmaxf(t, 0.f);
            p3[0][p] = fmaf(w0, h, p3[0][p]);
            p3[1][p] = fmaf(w1c, h, p3[1][p]);
            p3[2][p] = fmaf(w2c, h, p3[2][p]);
        }
    }
}

__device__ __forceinline__ void reduce3(float* red, float p3[3][8], int tx, int ty) {
#pragma unroll
    for (int k = 0; k < 3; ++k)
#pragma unroll
        for (int p = 0; p < 8; ++p) red[ty * 192 + k * 64 + 8 * tx + p] = p3[k][p];
    __syncthreads();
    for (int s = 16; s >= 1; s >>= 1) {
        if (ty < s) {
#pragma unroll
            for (int k = 0; k < 3; ++k)
#pragma unroll
                for (int p = 0; p < 8; ++p)
                    red[ty * 192 + k * 64 + 8 * tx + p] +=
                        red[(ty + s) * 192 + k * 64 + 8 * tx + p];
        }
        __syncthreads();
    }
}

// ================= K1 =================
__global__ __launch_bounds__(256) void k_gemm_mask(
    const float* __restrict__ F, const float* __restrict__ W1, const float* __restrict__ b1,
    const float* __restrict__ gg, const float* __restrict__ be, const float* __restrict__ mm,
    const float* __restrict__ vv, const float* __restrict__ W2, const float* __restrict__ b2,
    float* __restrict__ out) {
    extern __shared__ float sm[];
    float* fsm  = sm + SM_FSM;
    float* w2sm = sm + SM_W2;
    float* b2sm = sm + SM_B2;

    int b = blockIdx.y, n0 = blockIdx.x * TPTS, tid = threadIdx.x;
    int tx = tid & 7, ty = tid >> 3;

    for (int t = tid; t < 768; t += 256) w2sm[t] = W2[t];
    if (tid < 3) b2sm[tid] = b2[tid];

    float sc[8], bias2[8], b1v[8];
    bn_params(gg, be, mm, vv, b1, ty, sc, bias2, b1v);

    const float* Fb = F + (size_t)b * Cc * Np;
    for (int idx = tid; idx < 256 * TPTS; idx += 256) {
        int c = idx >> 6, p = idx & 63;
        int n = n0 + p;
        fsm[idx] = (n < Np) ? Fb[(size_t)c * Np + n] : 0.f;
    }
    __syncthreads();

    float acc[8][8];
    gemm_tile(W1, sm, tid, tx, ty, acc);

    float p3[3][8];
#pragma unroll
    for (int k = 0; k < 3; ++k)
#pragma unroll
        for (int p = 0; p < 8; ++p) p3[k][p] = 0.f;
    head3(w2sm, acc, sc, bias2, b1v, ty, p3);

    float* red = fsm;
    reduce3(red, p3, tx, ty);

    if (ty == 0) {
#pragma unroll
        for (int p = 0; p < 8; ++p) {
            int pt = 8 * tx + p;
            int n = n0 + pt;
            if (n < Np) {
                float s0 = __fadd_rn(red[pt], b2sm[0]);
                float s1 = __fadd_rn(red[64 + pt], b2sm[1]);
                float gr = __fadd_rn(red[128 + pt], b2sm[2]);
                out[OFF0 + (size_t)b * 2 * Np + n] = s0;
                out[OFF0 + (size_t)b * 2 * Np + Np + n] = s1;
                out[OFF1 + (size_t)b * Np + n] = gr;
                g_mask[b * Np + n] = (unsigned char)((s1 > s0) && (gr > 0.1f));
            }
        }
    }
}

// ================= K3: compaction + register-resident masked FPS =================
__device__ __forceinline__ void cmb(float& v, int& i, float v2, int i2) {
    if (v2 > v || (v2 == v && i2 < i)) { v = v2; i = i2; }
}

constexpr int RSLOT = 8;                       // 8*1024 = 8192 points in registers
constexpr int MAXOV = Np - RSLOT * 1024;       // 11808 overflow dists in smem
// smem byte offsets
constexpr int FP_DISTOV = 0;                   // MAXOV*4 = 47232
constexpr int FP_SEQ    = 47232;               // 1024*4
constexpr int FP_SLOTS  = 51328;               // 4 x u64 = 32
constexpr int FP_SBASE  = 51360;               // 4
constexpr int FP_WCNT   = 51392;               // 128
constexpr int FP_BYTES  = 51584;

__global__ __launch_bounds__(1024, 1) void k_fps(const float* __restrict__ xyz,
                                                 float* __restrict__ out) {
    extern __shared__ char smc[];
    float* distOv = (float*)(smc + FP_DISTOV);
    int*   seq    = (int*)(smc + FP_SEQ);
    unsigned long long* slots = (unsigned long long*)(smc + FP_SLOTS);
    int*   sBase  = (int*)(smc + FP_SBASE);
    int*   wcnt   = (int*)(smc + FP_WCNT);

    int b = blockIdx.x, tid = threadIdx.x, lane = tid & 31, wid = tid >> 5;
    const float* xb = xyz + (size_t)b * Np * 3;

    if (tid == 0) sBase[0] = 0;
    __syncthreads();

    // stable stream compaction of masked points
    for (int c0 = 0; c0 < Np; c0 += 1024) {
        int n = c0 + tid;
        bool mk = (n < Np) && g_mask[b * Np + n];
        unsigned bal = __ballot_sync(0xffffffffu, mk);
        int pre = __popc(bal & ((1u << lane) - 1u));
        if (lane == 0) wcnt[wid] = __popc(bal);
        __syncthreads();
        if (tid == 0) {
            int a = sBase[0];
            for (int w = 0; w < 32; ++w) { int t = wcnt[w]; wcnt[w] = a; a += t; }
            sBase[0] = a;
        }
        __syncthreads();
        if (mk) {
            int pos = wcnt[wid] + pre;
            g_cidx[b][pos] = n;
            g_cxyz[b][pos] = make_float4(xb[n * 3], xb[n * 3 + 1], xb[n * 3 + 2], 0.f);
        }
        __syncthreads();
    }
    int M = sBase[0];
    const float NEGINF = __int_as_float(0xff800000);

    // register-resident slots
    float rx[RSLOT], ry[RSLOT], rz[RSLOT], rd[RSLOT];
#pragma unroll
    for (int k = 0; k < RSLOT; ++k) {
        int i = k * 1024 + tid;
        if (i < M) {
            float4 p = g_cxyz[b][i];
            rx[k] = p.x; ry[k] = p.y; rz[k] = p.z; rd[k] = 1e10f;
        } else {
            rx[k] = 0.f; ry[k] = 0.f; rz[k] = 0.f; rd[k] = NEGINF;
        }
    }
    int Mov = M - RSLOT * 1024;  // may be negative
    for (int i = tid; i < Mov; i += 1024) distOv[i] = 1e10f;
    if (tid == 0) {
        seq[0] = 0;
        slots[0] = 0ull; slots[1] = 0ull; slots[2] = 0ull; slots[3] = 0ull;
    }
    __syncthreads();

    if (M > 0) {
        float4 p0 = g_cxyz[b][0];
        float px = p0.x, py = p0.y, pz = p0.z;
        for (int s = 1; s < NS; ++s) {
            float best = NEGINF;
            int bi = 0x7fffffff;
#pragma unroll
            for (int k = 0; k < RSLOT; ++k) {
                float dx = __fsub_rn(rx[k], px);
                float dy = __fsub_rn(ry[k], py);
                float dz = __fsub_rn(rz[k], pz);
                float d = __fadd_rn(__fadd_rn(__fmul_rn(dx, dx), __fmul_rn(dy, dy)),
                                    __fmul_rn(dz, dz));
                float nd = fminf(rd[k], d);
                rd[k] = nd;
                if (nd > best) { best = nd; bi = k * 1024 + tid; }
            }
            for (int i2 = tid; i2 < Mov; i2 += 1024) {  // overflow (rare)
                float4 p = g_cxyz[b][RSLOT * 1024 + i2];
                float dx = __fsub_rn(p.x, px);
                float dy = __fsub_rn(p.y, py);
                float dz = __fsub_rn(p.z, pz);
                float d = __fadd_rn(__fadd_rn(__fmul_rn(dx, dx), __fmul_rn(dy, dy)),
                                    __fmul_rn(dz, dz));
                float nd = fminf(distOv[i2], d);
                distOv[i2] = nd;
                if (nd > best) { best = nd; bi = RSLOT * 1024 + i2; }
            }
#pragma unroll
            for (int o = 16; o > 0; o >>= 1) {
                float v2 = __shfl_down_sync(0xffffffffu, best, o);
                int j2 = __shfl_down_sync(0xffffffffu, bi, o);
                cmb(best, bi, v2, j2);
            }
            int slot = s & 3;
            if (lane == 0 && bi != 0x7fffffff) {
                // dist >= 0 for real candidates -> float bits monotone; ~idx -> min-idx ties
                unsigned long long pk =
                    ((unsigned long long)__float_as_uint(best) << 32) |
                    (unsigned long long)(0xFFFFFFFFu - (unsigned)bi);
                atomicMax(&slots[slot], pk);
            }
            if (tid == 0) slots[(s + 2) & 3] = 0ull;  // safe: last read 2 steps ago
            __syncthreads();
            unsigned long long r = slots[slot];
            int win = (int)(0xFFFFFFFFu - (unsigned)(r & 0xFFFFFFFFull));
            if (tid == 0) seq[s] = win;
            float4 pw = g_cxyz[b][win];  // broadcast load
            px = pw.x; py = pw.y; pz = pw.z;
        }
    }
    __syncthreads();

    // epilogue: inds / xyz / fp2_graspness
    {
        int orig; float x, y, z;
        if (M > 0) {
            int c = seq[tid];
            orig = g_cidx[b][c];
            float4 p = g_cxyz[b][c];
            x = p.x; y = p.y; z = p.z;
        } else {
            orig = 0; x = xb[0]; y = xb[1]; z = xb[2];
        }
        out[OFF3 + (size_t)b * NS + tid] = (float)orig;
        out[OFF2 + (size_t)b * NS * 3 + tid * 3 + 0] = x;
        out[OFF2 + (size_t)b * NS * 3 + tid * 3 + 1] = y;
        out[OFF2 + (size_t)b * NS * 3 + tid * 3 + 2] = z;
        out[OFF5 + (size_t)b * NS + tid] = out[OFF1 + (size_t)b * Np + orig];
        g_sel[b][tid] = orig;
    }
}

// ================= K4 =================
__global__ __launch_bounds__(256) void k_view(
    const float* __restrict__ F, const float* __restrict__ W1, const float* __restrict__ b1,
    const float* __restrict__ gg, const float* __restrict__ be, const float* __restrict__ mm,
    const float* __restrict__ vv, const float* __restrict__ W2, const float* __restrict__ b2,
    float* __restrict__ out) {
    extern __shared__ float sm[];
    float* fsm  = sm + SM_FSM;
    float* w2sm = sm + SM_W2;
    float* b2sm = sm + SM_B2;
    float* vsm  = sm + SM_VSM;
    int*   idxs = (int*)(sm + SM_IDX);
    float* vps  = sm + SM_VPS;

    int b = blockIdx.y, s0 = blockIdx.x * TPTS, tid = threadIdx.x;
    int tx = tid & 7, ty = tid >> 3;

    if (tid < TPTS) idxs[tid] = g_sel[b][s0 + tid];
    for (int t = tid; t < 768; t += 256) w2sm[t] = W2[t];
    if (tid < 3) b2sm[tid] = b2[tid];

    for (int i = tid; i < NV; i += 256) {
        double z = (2.0 * (double)i + 1.0) / (double)NV - 1.0;
        double r = sqrt(fmax(1.0 - z * z, 0.0));
        double phi = (sqrt(5.0) - 1.0) / 2.0;
        double ang = (2.0 * 3.14159265358979323846) * (double)i * phi;
        float x = (float)(r * cos(ang)), y = (float)(r * sin(ang)), zf = (float)z;
        float nr2 = __fadd_rn(__fadd_rn(__fmul_rn(x, x), __fmul_rn(y, y)), __fmul_rn(zf, zf));
        float nr = fmaxf(sqrtf(nr2), 1e-8f);
        vsm[i * 3 + 0] = __fdiv_rn(x, nr);
        vsm[i * 3 + 1] = __fdiv_rn(y, nr);
        vsm[i * 3 + 2] = __fdiv_rn(zf, nr);
    }

    float sc[8], bias2[8], b1v[8];
    bn_params(gg, be, mm, vv, b1, ty, sc, bias2, b1v);
    __syncthreads();

    const float* Fb = F + (size_t)b * Cc * Np;
    for (int idx = tid; idx < 256 * TPTS; idx += 256) {
        int c = idx >> 6, s = idx & 63;
        float val = Fb[(size_t)c * Np + idxs[s]];
        fsm[idx] = val;
        out[OFF4 + (size_t)b * Cc * NS + (size_t)c * NS + s0 + s] = val;
    }
    __syncthreads();

    float acc[8][8];
    gemm_tile(W1, sm, tid, tx, ty, acc);

    float p3[3][8];
#pragma unroll
    for (int k = 0; k < 3; ++k)
#pragma unroll
        for (int p = 0; p < 8; ++p) p3[k][p] = 0.f;
    head3(w2sm, acc, sc, bias2, b1v, ty, p3);

    float* red = fsm;
    reduce3(red, p3, tx, ty);

    if (ty == 0) {
#pragma unroll
        for (int p = 0; p < 8; ++p) {
            int pt = 8 * tx + p;
            int s = s0 + pt;
            float v0 = __fadd_rn(red[pt], b2sm[0]);
            float v1 = __fadd_rn(red[64 + pt], b2sm[1]);
            float v2 = __fadd_rn(red[128 + pt], b2sm[2]);
            out[OFF6 + (size_t)b * NS * 3 + (size_t)s * 3 + 0] = v0;
            out[OFF6 + (size_t)b * NS * 3 + (size_t)s * 3 + 1] = v1;
            out[OFF6 + (size_t)b * NS * 3 + (size_t)s * 3 + 2] = v2;
            vps[pt * 3 + 0] = v0; vps[pt * 3 + 1] = v1; vps[pt * 3 + 2] = v2;
        }
    }
    __syncthreads();

    if (tid < TPTS) {
        int s = s0 + tid;
        float vx = vps[tid * 3], vy = vps[tid * 3 + 1], vz = vps[tid * 3 + 2];
        float n2 = __fadd_rn(__fadd_rn(__fmul_rn(vx, vx), __fmul_rn(vy, vy)), __fmul_rn(vz, vz));
        float nr = fmaxf(sqrtf(n2), 1e-8f);
        float ax_ = __fdiv_rn(vx, nr), ay_ = __fdiv_rn(vy, nr), az_ = __fdiv_rn(vz, nr);
        float best = __int_as_float(0xff800000);
        int bi = 0;
        for (int v = 0; v < NV; ++v) {
            float c = __fadd_rn(__fadd_rn(__fmul_rn(ax_, vsm[v * 3]),
                                          __fmul_rn(ay_, vsm[v * 3 + 1])),
                                __fmul_rn(az_, vsm[v * 3 + 2]));
            if (c > best) { best = c; bi = v; }
        }
        out[OFF7 + (size_t)b * NS + s] = (float)bi;

        float tx0 = -vx, tx1 = -vy, tx2 = -vz;
        float ay0 = -tx1, ay1 = tx0, ay2 = 0.f;
        float s2 = ay0 * ay0 + ay1 * ay1;
        if (s2 == 0.f) { ay0 = 0.f; ay1 = 1.f; ay2 = 0.f; }
        float an = sqrtf(tx0 * tx0 + tx1 * tx1 + tx2 * tx2);
        float nx0 = tx0 / an, nx1 = tx1 / an, nx2 = tx2 / an;
        float bn = sqrtf(ay0 * ay0 + ay1 * ay1 + ay2 * ay2);
        float ny0 = ay0 / bn, ny1 = ay1 / bn, ny2 = ay2 / bn;
        float nz0 = nx1 * ny2 - nx2 * ny1;
        float nz1 = nx2 * ny0 - nx0 * ny2;
        float nz2 = nx0 * ny1 - nx1 * ny0;
        size_t base = OFF8 + ((size_t)b * NS + s) * 9;
        out[base + 0] = nx0; out[base + 1] = ny0; out[base + 2] = nz0;
        out[base + 3] = nx1; out[base + 4] = ny1; out[base + 5] = nz1;
        out[base + 6] = nx2; out[base + 7] = ny2; out[base + 8] = nz2;
    }
}

// ================= launch (robust input-order detection) =================
extern "C" void kernel_launch(void* const* d_in, const int* in_sizes, int n_in,
                              void* d_out, int out_size) {
    const float *xyz, *F, *w1, *b1, *gg, *be, *mm, *vv, *w2, *b2;
    const float *c1w, *c1b, *bng, *bnb, *bnm, *bnv, *c2w, *c2b;

    int imax = 0;
    for (int i = 1; i < n_in; ++i)
        if (in_sizes[i] > in_sizes[imax]) imax = i;

    if (imax == 1) {  // dict-insertion / signature order
        xyz = (const float*)d_in[0];  F   = (const float*)d_in[1];
        w1  = (const float*)d_in[2];  b1  = (const float*)d_in[3];
        gg  = (const float*)d_in[4];  be  = (const float*)d_in[5];
        mm  = (const float*)d_in[6];  vv  = (const float*)d_in[7];
        w2  = (const float*)d_in[8];  b2  = (const float*)d_in[9];
        c1w = (const float*)d_in[10]; c1b = (const float*)d_in[11];
        bng = (const float*)d_in[12]; bnb = (const float*)d_in[13];
        bnm = (const float*)d_in[14]; bnv = (const float*)d_in[15];
        c2w = (const float*)d_in[16]; c2b = (const float*)d_in[17];
    } else {          // alphabetical order (seed_features at 16)
        bnb = (const float*)d_in[0];  bng = (const float*)d_in[1];
        bnm = (const float*)d_in[2];  bnv = (const float*)d_in[3];
        c1b = (const float*)d_in[4];  c1w = (const float*)d_in[5];
        c2b = (const float*)d_in[6];  c2w = (const float*)d_in[7];
        b1  = (const float*)d_in[8];  b2  = (const float*)d_in[9];
        be  = (const float*)d_in[10]; gg  = (const float*)d_in[11];
        mm  = (const float*)d_in[12]; vv  = (const float*)d_in[13];
        w1  = (const float*)d_in[14]; w2  = (const float*)d_in[15];
        F   = (const float*)d_in[16]; xyz = (const float*)d_in[17];
    }
    float* out = (float*)d_out;

    const int SM1 = SM1_FLOATS * 4;
    const int SM3 = FP_BYTES;
    const int SM4 = SM4_FLOATS * 4;
    cudaFuncSetAttribute(k_gemm_mask, cudaFuncAttributeMaxDynamicSharedMemorySize, SM1);
    cudaFuncSetAttribute(k_fps, cudaFuncAttributeMaxDynamicSharedMemorySize, SM3);
    cudaFuncSetAttribute(k_view, cudaFuncAttributeMaxDynamicSharedMemorySize, SM4);

    dim3 g1((Np + TPTS - 1) / TPTS, Bb);
    k_gemm_mask<<<g1, 256, SM1>>>(F, w1, b1, gg, be, mm, vv, w2, b2, out);
    k_fps<<<Bb, 1024, SM3>>>(xyz, out);
    dim3 g4(NS / TPTS, Bb);
    k_view<<<g4, 256, SM4>>>(F, c1w, c1b, bng, bnb, bnm, bnv, c2w, c2b, out);
}

// round 7
// speedup vs baseline: 1.1081x; 1.1081x over previous
#include <cuda_runtime.h>
#include <cuda_bf16.h>
#include <math.h>
#include <stdint.h>

constexpr int Bb = 4;
constexpr int Np = 20000;
constexpr int Cc = 256;
constexpr int NS = 1024;
constexpr int NV = 300;

// output offsets (float32 elements), reference return order, row-major flatten
constexpr size_t OFF0 = 0;        // objectness (B,2,N)
constexpr size_t OFF1 = 160000;   // graspness (B,N)
constexpr size_t OFF2 = 240000;   // graspable_xyz (B,NS,3)
constexpr size_t OFF3 = 252288;   // graspable_inds (B,NS)
constexpr size_t OFF4 = 256384;   // graspable_features (B,C,NS)
constexpr size_t OFF5 = 1304960;  // fp2_graspness (B,NS)
constexpr size_t OFF6 = 1309056;  // vp_xyz (B,NS,3)
constexpr size_t OFF7 = 1321344;  // top_view_inds (B,NS)
constexpr size_t OFF8 = 1325440;  // vp_rot (B,NS,3,3)

__device__ unsigned char g_mask[Bb * Np];
__device__ int    g_cidx[Bb][Np];
__device__ float4 g_cxyz[Bb][Np];
__device__ int    g_sel[Bb][NS];

// ---------- f32x2 helpers ----------
__device__ __forceinline__ unsigned long long pk2(float a, float b) {
    unsigned long long r;
    asm("mov.b64 %0, {%1, %2};" : "=l"(r) : "f"(a), "f"(b));
    return r;
}
__device__ __forceinline__ void up2(unsigned long long v, float& a, float& b) {
    asm("mov.b64 {%0, %1}, %2;" : "=f"(a), "=f"(b) : "l"(v));
}
__device__ __forceinline__ unsigned long long fma2(unsigned long long a, unsigned long long b,
                                                   unsigned long long c) {
    unsigned long long d;
    asm("fma.rn.f32x2 %0, %1, %2, %3;" : "=l"(d) : "l"(a), "l"(b), "l"(c));
    return d;
}

// ---------- GEMM tile constants (64 points x 256 co per block) ----------
constexpr int TPTS = 64;
constexpr int SM_FSM = 0;        // 16384 floats
constexpr int SM_WSM = 16384;    // 2 x 2048 floats (double buffer)
constexpr int SM_W2  = 20480;    // 768
constexpr int SM_B2  = 21248;    // 4
constexpr int SM1_FLOATS = 21252;
constexpr int SM_VSM = 21252;    // 900
constexpr int SM_IDX = 22152;    // 64 ints
constexpr int SM_VPS = 22216;    // 192
constexpr int SM4_FLOATS = 22408;

__device__ __forceinline__ void wstore(float* wbuf, int tid, float4 a, float4 b) {
    wbuf[0 * 256 + tid] = a.x; wbuf[1 * 256 + tid] = a.y;
    wbuf[2 * 256 + tid] = a.z; wbuf[3 * 256 + tid] = a.w;
    wbuf[4 * 256 + tid] = b.x; wbuf[5 * 256 + tid] = b.y;
    wbuf[6 * 256 + tid] = b.z; wbuf[7 * 256 + tid] = b.w;
}

// tx=tid&7 owns pts 8tx..8tx+7, ty=tid>>3 owns co 8ty..8ty+7.
__device__ __forceinline__ void gemm_tile(const float* __restrict__ W, float* sm,
                                          int tid, int tx, int ty, float acc[8][8]) {
    float* fsm = sm + SM_FSM;
    float* wsm = sm + SM_WSM;
    unsigned long long acc2[8][4];
#pragma unroll
    for (int j = 0; j < 8; ++j)
#pragma unroll
        for (int q = 0; q < 4; ++q) acc2[j][q] = 0ull;

    // preload ck=0 into buffer 0
    {
        const float4* srcw = reinterpret_cast<const float4*>(W + tid * 256);
        wstore(wsm, tid, srcw[0], srcw[1]);
    }
    __syncthreads();

    for (int ck = 0; ck < 32; ++ck) {
        float4 na, nb;
        if (ck < 31) {  // prefetch next W chunk (LDG overlaps compute)
            const float4* srcw =
                reinterpret_cast<const float4*>(W + tid * 256 + (ck + 1) * 8);
            na = srcw[0]; nb = srcw[1];
        }
        const float* wbuf = wsm + (ck & 1) * 2048;
#pragma unroll
        for (int ci = 0; ci < 8; ++ci) {
            const float* wrow = wbuf + ci * 256 + 8 * ty;
            float4 wa = *reinterpret_cast<const float4*>(wrow);
            float4 wb = *reinterpret_cast<const float4*>(wrow + 4);
            const float* frow = fsm + (ck * 8 + ci) * TPTS + 8 * tx;
            float4 fa = *reinterpret_cast<const float4*>(frow);
            float4 fb = *reinterpret_cast<const float4*>(frow + 4);
            unsigned long long f2[4] = {pk2(fa.x, fa.y), pk2(fa.z, fa.w),
                                        pk2(fb.x, fb.y), pk2(fb.z, fb.w)};
            float w[8] = {wa.x, wa.y, wa.z, wa.w, wb.x, wb.y, wb.z, wb.w};
#pragma unroll
            for (int j = 0; j < 8; ++j) {
                unsigned long long wd = pk2(w[j], w[j]);
#pragma unroll
                for (int q = 0; q < 4; ++q) acc2[j][q] = fma2(f2[q], wd, acc2[j][q]);
            }
        }
        if (ck < 31) wstore(wsm + ((ck + 1) & 1) * 2048, tid, na, nb);
        __syncthreads();
    }
#pragma unroll
    for (int j = 0; j < 8; ++j)
#pragma unroll
        for (int q = 0; q < 4; ++q) up2(acc2[j][q], acc[j][2 * q], acc[j][2 * q + 1]);
}

__device__ __forceinline__ void bn_params(const float* gg, const float* be, const float* mm,
                                          const float* vv, const float* b1, int ty,
                                          float sc[8], float bias2[8], float b1v[8]) {
#pragma unroll
    for (int j = 0; j < 8; ++j) {
        int co = 8 * ty + j;
        float s = __fdiv_rn(gg[co], sqrtf(__fadd_rn(vv[co], 1e-5f)));
        sc[j] = s;
        bias2[j] = __fsub_rn(be[co], __fmul_rn(mm[co], s));
        b1v[j] = b1[co];
    }
}

__device__ __forceinline__ void head3(const float* w2sm, float acc[8][8],
                                      const float sc[8], const float bias2[8],
                                      const float b1v[8], int ty, float p3[3][8]) {
#pragma unroll
    for (int j = 0; j < 8; ++j) {
        int co = 8 * ty + j;
        float w0 = w2sm[co], w1c = w2sm[256 + co], w2c = w2sm[512 + co];
#pragma unroll
        for (int p = 0; p < 8; ++p) {
            float t = __fadd_rn(acc[j][p], b1v[j]);
            t = __fmul_rn(t, sc[j]);
            t = __fadd_rn(t, bias2[j]);
            float h = fmaxf(t, 0.f);
            p3[0][p] = fmaf(w0, h, p3[0][p]);
            p3[1][p] = fmaf(w1c, h, p3[1][p]);
            p3[2][p] = fmaf(w2c, h, p3[2][p]);
        }
    }
}

__device__ __forceinline__ void reduce3(float* red, float p3[3][8], int tx, int ty) {
#pragma unroll
    for (int k = 0; k < 3; ++k)
#pragma unroll
        for (int p = 0; p < 8; ++p) red[ty * 192 + k * 64 + 8 * tx + p] = p3[k][p];
    __syncthreads();
    for (int s = 16; s >= 1; s >>= 1) {
        if (ty < s) {
#pragma unroll
            for (int k = 0; k < 3; ++k)
#pragma unroll
                for (int p = 0; p < 8; ++p)
                    red[ty * 192 + k * 64 + 8 * tx + p] +=
                        red[(ty + s) * 192 + k * 64 + 8 * tx + p];
        }
        __syncthreads();
    }
}

// ================= K1 =================
__global__ __launch_bounds__(256) void k_gemm_mask(
    const float* __restrict__ F, const float* __restrict__ W1, const float* __restrict__ b1,
    const float* __restrict__ gg, const float* __restrict__ be, const float* __restrict__ mm,
    const float* __restrict__ vv, const float* __restrict__ W2, const float* __restrict__ b2,
    float* __restrict__ out) {
    extern __shared__ float sm[];
    float* fsm  = sm + SM_FSM;
    float* w2sm = sm + SM_W2;
    float* b2sm = sm + SM_B2;

    int b = blockIdx.y, n0 = blockIdx.x * TPTS, tid = threadIdx.x;
    int tx = tid & 7, ty = tid >> 3;

    for (int t = tid; t < 768; t += 256) w2sm[t] = W2[t];
    if (tid < 3) b2sm[tid] = b2[tid];

    float sc[8], bias2[8], b1v[8];
    bn_params(gg, be, mm, vv, b1, ty, sc, bias2, b1v);

    const float* Fb = F + (size_t)b * Cc * Np;
    for (int idx = tid; idx < 256 * TPTS; idx += 256) {
        int c = idx >> 6, p = idx & 63;
        int n = n0 + p;
        fsm[idx] = (n < Np) ? Fb[(size_t)c * Np + n] : 0.f;
    }
    __syncthreads();

    float acc[8][8];
    gemm_tile(W1, sm, tid, tx, ty, acc);

    float p3[3][8];
#pragma unroll
    for (int k = 0; k < 3; ++k)
#pragma unroll
        for (int p = 0; p < 8; ++p) p3[k][p] = 0.f;
    head3(w2sm, acc, sc, bias2, b1v, ty, p3);

    float* red = fsm;
    reduce3(red, p3, tx, ty);

    if (ty == 0) {
#pragma unroll
        for (int p = 0; p < 8; ++p) {
            int pt = 8 * tx + p;
            int n = n0 + pt;
            if (n < Np) {
                float s0 = __fadd_rn(red[pt], b2sm[0]);
                float s1 = __fadd_rn(red[64 + pt], b2sm[1]);
                float gr = __fadd_rn(red[128 + pt], b2sm[2]);
                out[OFF0 + (size_t)b * 2 * Np + n] = s0;
                out[OFF0 + (size_t)b * 2 * Np + Np + n] = s1;
                out[OFF1 + (size_t)b * Np + n] = gr;
                g_mask[b * Np + n] = (unsigned char)((s1 > s0) && (gr > 0.1f));
            }
        }
    }
}

// ================= K3: smem-xyz + register-dist masked FPS =================
constexpr int SMPTS = 10240;                 // 10 slots x 1024 threads in smem xyz
constexpr int RSLOT = 10;                    // dist registers (no spill at 1024 thr)
// smem byte offsets
constexpr int FP_SXYZ   = 0;                 // SMPTS*16 = 163840
constexpr int FP_SEQ    = 163840;            // 1024*4
constexpr int FP_RED    = 167936;            // 2 x 32 x u64 = 512
constexpr int FP_WCNT   = 168448;            // 128
constexpr int FP_SBASE  = 168576;            // 4 (+pad)
constexpr int FP_DISTOV = 168832;            // (Np-SMPTS)*4 = 39040
constexpr int FP_BYTES  = 207872;

__global__ __launch_bounds__(1024, 1) void k_fps(const float* __restrict__ xyz,
                                                 float* __restrict__ out) {
    extern __shared__ char smc[];
    float4* sxyz  = (float4*)(smc + FP_SXYZ);
    int*    seq   = (int*)(smc + FP_SEQ);
    unsigned long long* red = (unsigned long long*)(smc + FP_RED);
    int*    wcnt  = (int*)(smc + FP_WCNT);
    int*    sBase = (int*)(smc + FP_SBASE);
    float*  distOv= (float*)(smc + FP_DISTOV);

    int b = blockIdx.x, tid = threadIdx.x, lane = tid & 31, wid = tid >> 5;
    const float* xb = xyz + (size_t)b * Np * 3;

    if (tid == 0) sBase[0] = 0;
    __syncthreads();

    // stable stream compaction of masked points (writes smem xyz + global mirror)
    for (int c0 = 0; c0 < Np; c0 += 1024) {
        int n = c0 + tid;
        bool mk = (n < Np) && g_mask[b * Np + n];
        unsigned bal = __ballot_sync(0xffffffffu, mk);
        int pre = __popc(bal & ((1u << lane) - 1u));
        if (lane == 0) wcnt[wid] = __popc(bal);
        __syncthreads();
        if (tid == 0) {
            int a = sBase[0];
            for (int w = 0; w < 32; ++w) { int t = wcnt[w]; wcnt[w] = a; a += t; }
            sBase[0] = a;
        }
        __syncthreads();
        if (mk) {
            int pos = wcnt[wid] + pre;
            float4 p = make_float4(xb[n * 3], xb[n * 3 + 1], xb[n * 3 + 2], 0.f);
            g_cidx[b][pos] = n;
            g_cxyz[b][pos] = p;
            if (pos < SMPTS) sxyz[pos] = p;
        }
        __syncthreads();
    }
    int M = sBase[0];
    const float NEGINF = __int_as_float(0xff800000);

    float rd[RSLOT];
#pragma unroll
    for (int k = 0; k < RSLOT; ++k)
        rd[k] = (k * 1024 + tid < M) ? 1e10f : NEGINF;
    for (int i = tid; i < M - SMPTS; i += 1024) distOv[i] = 1e10f;
    if (tid == 0) seq[0] = 0;
    __syncthreads();

    if (M > 0) {
        float4 p0 = sxyz[0];
        float px = p0.x, py = p0.y, pz = p0.z;
        for (int s = 1; s < NS; ++s) {
            float best = NEGINF;
            int bi = 0x7fffffff;
#pragma unroll
            for (int k = 0; k < RSLOT; ++k) {
                if (k * 1024 < M) {  // uniform branch
                    int i = k * 1024 + tid;
                    float4 p = sxyz[i];   // i < SMPTS always; beyond-M reads harmless
                    float dx = __fsub_rn(p.x, px);
                    float dy = __fsub_rn(p.y, py);
                    float dz = __fsub_rn(p.z, pz);
                    float d = __fadd_rn(__fadd_rn(__fmul_rn(dx, dx), __fmul_rn(dy, dy)),
                                        __fmul_rn(dz, dz));
                    float nd = fminf(rd[k], d);
                    rd[k] = nd;
                    if (nd > best) { best = nd; bi = i; }
                }
            }
            for (int i = SMPTS + tid; i < M; i += 1024) {  // overflow (rare)
                float4 p = g_cxyz[b][i];
                float dx = __fsub_rn(p.x, px);
                float dy = __fsub_rn(p.y, py);
                float dz = __fsub_rn(p.z, pz);
                float d = __fadd_rn(__fadd_rn(__fmul_rn(dx, dx), __fmul_rn(dy, dy)),
                                    __fmul_rn(dz, dz));
                float nd = fminf(distOv[i - SMPTS], d);
                distOv[i - SMPTS] = nd;
                if (nd > best) { best = nd; bi = i; }
            }
            // packed (dist_bits, ~idx): max => largest dist, ties -> smallest idx
            unsigned long long pk = (bi != 0x7fffffff)
                ? (((unsigned long long)__float_as_uint(best) << 32) |
                   (unsigned long long)(0xFFFFFFFFu - (unsigned)bi))
                : 0ull;
#pragma unroll
            for (int o = 16; o > 0; o >>= 1) {
                unsigned long long q = __shfl_xor_sync(0xffffffffu, pk, o);
                if (q > pk) pk = q;
            }
            int buf = (s & 1) * 32;
            if (lane == 0) red[buf + wid] = pk;
            __syncthreads();
            unsigned long long v = red[buf + lane];
#pragma unroll
            for (int o = 16; o > 0; o >>= 1) {
                unsigned long long q = __shfl_xor_sync(0xffffffffu, v, o);
                if (q > v) v = q;
            }
            int win = (int)(0xFFFFFFFFu - (unsigned)(v & 0xFFFFFFFFull));
            if (tid == 0) seq[s] = win;
            float4 pw = (win < SMPTS) ? sxyz[win] : g_cxyz[b][win];
            px = pw.x; py = pw.y; pz = pw.z;
        }
    }
    __syncthreads();

    // epilogue: inds / xyz / fp2_graspness
    {
        int orig; float x, y, z;
        if (M > 0) {
            int c = seq[tid];
            orig = g_cidx[b][c];
            float4 p = g_cxyz[b][c];
            x = p.x; y = p.y; z = p.z;
        } else {
            orig = 0; x = xb[0]; y = xb[1]; z = xb[2];
        }
        out[OFF3 + (size_t)b * NS + tid] = (float)orig;
        out[OFF2 + (size_t)b * NS * 3 + tid * 3 + 0] = x;
        out[OFF2 + (size_t)b * NS * 3 + tid * 3 + 1] = y;
        out[OFF2 + (size_t)b * NS * 3 + tid * 3 + 2] = z;
        out[OFF5 + (size_t)b * NS + tid] = out[OFF1 + (size_t)b * Np + orig];
        g_sel[b][tid] = orig;
    }
}

// ================= K4 =================
__global__ __launch_bounds__(256) void k_view(
    const float* __restrict__ F, const float* __restrict__ W1, const float* __restrict__ b1,
    const float* __restrict__ gg, const float* __restrict__ be, const float* __restrict__ mm,
    const float* __restrict__ vv, const float* __restrict__ W2, const float* __restrict__ b2,
    float* __restrict__ out) {
    extern __shared__ float sm[];
    float* fsm  = sm + SM_FSM;
    float* w2sm = sm + SM_W2;
    float* b2sm = sm + SM_B2;
    float* vsm  = sm + SM_VSM;
    int*   idxs = (int*)(sm + SM_IDX);
    float* vps  = sm + SM_VPS;

    int b = blockIdx.y, s0 = blockIdx.x * TPTS, tid = threadIdx.x;
    int tx = tid & 7, ty = tid >> 3;

    if (tid < TPTS) idxs[tid] = g_sel[b][s0 + tid];
    for (int t = tid; t < 768; t += 256) w2sm[t] = W2[t];
    if (tid < 3) b2sm[tid] = b2[tid];

    for (int i = tid; i < NV; i += 256) {
        double z = (2.0 * (double)i + 1.0) / (double)NV - 1.0;
        double r = sqrt(fmax(1.0 - z * z, 0.0));
        double phi = (sqrt(5.0) - 1.0) / 2.0;
        double ang = (2.0 * 3.14159265358979323846) * (double)i * phi;
        float x = (float)(r * cos(ang)), y = (float)(r * sin(ang)), zf = (float)z;
        float nr2 = __fadd_rn(__fadd_rn(__fmul_rn(x, x), __fmul_rn(y, y)), __fmul_rn(zf, zf));
        float nr = fmaxf(sqrtf(nr2), 1e-8f);
        vsm[i * 3 + 0] = __fdiv_rn(x, nr);
        vsm[i * 3 + 1] = __fdiv_rn(y, nr);
        vsm[i * 3 + 2] = __fdiv_rn(zf, nr);
    }

    float sc[8], bias2[8], b1v[8];
    bn_params(gg, be, mm, vv, b1, ty, sc, bias2, b1v);
    __syncthreads();

    const float* Fb = F + (size_t)b * Cc * Np;
    for (int idx = tid; idx < 256 * TPTS; idx += 256) {
        int c = idx >> 6, s = idx & 63;
        float val = Fb[(size_t)c * Np + idxs[s]];
        fsm[idx] = val;
        out[OFF4 + (size_t)b * Cc * NS + (size_t)c * NS + s0 + s] = val;
    }
    __syncthreads();

    float acc[8][8];
    gemm_tile(W1, sm, tid, tx, ty, acc);

    float p3[3][8];
#pragma unroll
    for (int k = 0; k < 3; ++k)
#pragma unroll
        for (int p = 0; p < 8; ++p) p3[k][p] = 0.f;
    head3(w2sm, acc, sc, bias2, b1v, ty, p3);

    float* red = fsm;
    reduce3(red, p3, tx, ty);

    if (ty == 0) {
#pragma unroll
        for (int p = 0; p < 8; ++p) {
            int pt = 8 * tx + p;
            int s = s0 + pt;
            float v0 = __fadd_rn(red[pt], b2sm[0]);
            float v1 = __fadd_rn(red[64 + pt], b2sm[1]);
            float v2 = __fadd_rn(red[128 + pt], b2sm[2]);
            out[OFF6 + (size_t)b * NS * 3 + (size_t)s * 3 + 0] = v0;
            out[OFF6 + (size_t)b * NS * 3 + (size_t)s * 3 + 1] = v1;
            out[OFF6 + (size_t)b * NS * 3 + (size_t)s * 3 + 2] = v2;
            vps[pt * 3 + 0] = v0; vps[pt * 3 + 1] = v1; vps[pt * 3 + 2] = v2;
        }
    }
    __syncthreads();

    if (tid < TPTS) {
        int s = s0 + tid;
        float vx = vps[tid * 3], vy = vps[tid * 3 + 1], vz = vps[tid * 3 + 2];
        float n2 = __fadd_rn(__fadd_rn(__fmul_rn(vx, vx), __fmul_rn(vy, vy)), __fmul_rn(vz, vz));
        float nr = fmaxf(sqrtf(n2), 1e-8f);
        float ax_ = __fdiv_rn(vx, nr), ay_ = __fdiv_rn(vy, nr), az_ = __fdiv_rn(vz, nr);
        float best = __int_as_float(0xff800000);
        int bi = 0;
        for (int v = 0; v < NV; ++v) {
            float c = __fadd_rn(__fadd_rn(__fmul_rn(ax_, vsm[v * 3]),
                                          __fmul_rn(ay_, vsm[v * 3 + 1])),
                                __fmul_rn(az_, vsm[v * 3 + 2]));
            if (c > best) { best = c; bi = v; }
        }
        out[OFF7 + (size_t)b * NS + s] = (float)bi;

        float tx0 = -vx, tx1 = -vy, tx2 = -vz;
        float ay0 = -tx1, ay1 = tx0, ay2 = 0.f;
        float s2 = ay0 * ay0 + ay1 * ay1;
        if (s2 == 0.f) { ay0 = 0.f; ay1 = 1.f; ay2 = 0.f; }
        float an = sqrtf(tx0 * tx0 + tx1 * tx1 + tx2 * tx2);
        float nx0 = tx0 / an, nx1 = tx1 / an, nx2 = tx2 / an;
        float bn = sqrtf(ay0 * ay0 + ay1 * ay1 + ay2 * ay2);
        float ny0 = ay0 / bn, ny1 = ay1 / bn, ny2 = ay2 / bn;
        float nz0 = nx1 * ny2 - nx2 * ny1;
        float nz1 = nx2 * ny0 - nx0 * ny2;
        float nz2 = nx0 * ny1 - nx1 * ny0;
        size_t base = OFF8 + ((size_t)b * NS + s) * 9;
        out[base + 0] = nx0; out[base + 1] = ny0; out[base + 2] = nz0;
        out[base + 3] = nx1; out[base + 4] = ny1; out[base + 5] = nz1;
        out[base + 6] = nx2; out[base + 7] = ny2; out[base + 8] = nz2;
    }
}

// ================= launch (robust input-order detection) =================
extern "C" void kernel_launch(void* const* d_in, const int* in_sizes, int n_in,
                              void* d_out, int out_size) {
    const float *xyz, *F, *w1, *b1, *gg, *be, *mm, *vv, *w2, *b2;
    const float *c1w, *c1b, *bng, *bnb, *bnm, *bnv, *c2w, *c2b;

    int imax = 0;
    for (int i = 1; i < n_in; ++i)
        if (in_sizes[i] > in_sizes[imax]) imax = i;

    if (imax == 1) {  // dict-insertion / signature order
        xyz = (const float*)d_in[0];  F   = (const float*)d_in[1];
        w1  = (const float*)d_in[2];  b1  = (const float*)d_in[3];
        gg  = (const float*)d_in[4];  be  = (const float*)d_in[5];
        mm  = (const float*)d_in[6];  vv  = (const float*)d_in[7];
        w2  = (const float*)d_in[8];  b2  = (const float*)d_in[9];
        c1w = (const float*)d_in[10]; c1b = (const float*)d_in[11];
        bng = (const float*)d_in[12]; bnb = (const float*)d_in[13];
        bnm = (const float*)d_in[14]; bnv = (const float*)d_in[15];
        c2w = (const float*)d_in[16]; c2b = (const float*)d_in[17];
    } else {          // alphabetical order
        bnb = (const float*)d_in[0];  bng = (const float*)d_in[1];
        bnm = (const float*)d_in[2];  bnv = (const float*)d_in[3];
        c1b = (const float*)d_in[4];  c1w = (const float*)d_in[5];
        c2b = (const float*)d_in[6];  c2w = (const float*)d_in[7];
        b1  = (const float*)d_in[8];  b2  = (const float*)d_in[9];
        be  = (const float*)d_in[10]; gg  = (const float*)d_in[11];
        mm  = (const float*)d_in[12]; vv  = (const float*)d_in[13];
        w1  = (const float*)d_in[14]; w2  = (const float*)d_in[15];
        F   = (const float*)d_in[16]; xyz = (const float*)d_in[17];
    }
    float* out = (float*)d_out;

    const int SM1 = SM1_FLOATS * 4;
    const int SM3 = FP_BYTES;
    const int SM4 = SM4_FLOATS * 4;
    cudaFuncSetAttribute(k_gemm_mask, cudaFuncAttributeMaxDynamicSharedMemorySize, SM1);
    cudaFuncSetAttribute(k_fps, cudaFuncAttributeMaxDynamicSharedMemorySize, SM3);
    cudaFuncSetAttribute(k_view, cudaFuncAttributeMaxDynamicSharedMemorySize, SM4);

    dim3 g1((Np + TPTS - 1) / TPTS, Bb);
    k_gemm_mask<<<g1, 256, SM1>>>(F, w1, b1, gg, be, mm, vv, w2, b2, out);
    k_fps<<<Bb, 1024, SM3>>>(xyz, out);
    dim3 g4(NS / TPTS, Bb);
    k_view<<<g4, 256, SM4>>>(F, c1w, c1b, bng, bnb, bnm, bnv, c2w, c2b, out);
}

// round 8
// speedup vs baseline: 1.4775x; 1.3334x over previous
#include <cuda_runtime.h>
#include <cuda_bf16.h>
#include <math.h>
#include <stdint.h>

constexpr int Bb = 4;
constexpr int Np = 20000;
constexpr int Cc = 256;
constexpr int NS = 1024;
constexpr int NV = 300;

// output offsets (float32 elements), reference return order, row-major flatten
constexpr size_t OFF0 = 0;        // objectness (B,2,N)
constexpr size_t OFF1 = 160000;   // graspness (B,N)
constexpr size_t OFF2 = 240000;   // graspable_xyz (B,NS,3)
constexpr size_t OFF3 = 252288;   // graspable_inds (B,NS)
constexpr size_t OFF4 = 256384;   // graspable_features (B,C,NS)
constexpr size_t OFF5 = 1304960;  // fp2_graspness (B,NS)
constexpr size_t OFF6 = 1309056;  // vp_xyz (B,NS,3)
constexpr size_t OFF7 = 1321344;  // top_view_inds (B,NS)
constexpr size_t OFF8 = 1325440;  // vp_rot (B,NS,3,3)

__device__ unsigned char g_mask[Bb * Np];
__device__ int    g_cidx[Bb][Np];
__device__ float4 g_cxyz[Bb][Np];
__device__ int    g_sel[Bb][NS];

// ---------- f32x2 helpers ----------
__device__ __forceinline__ unsigned long long pk2(float a, float b) {
    unsigned long long r;
    asm("mov.b64 %0, {%1, %2};" : "=l"(r) : "f"(a), "f"(b));
    return r;
}
__device__ __forceinline__ void up2(unsigned long long v, float& a, float& b) {
    asm("mov.b64 {%0, %1}, %2;" : "=f"(a), "=f"(b) : "l"(v));
}
__device__ __forceinline__ unsigned long long fma2(unsigned long long a, unsigned long long b,
                                                   unsigned long long c) {
    unsigned long long d;
    asm("fma.rn.f32x2 %0, %1, %2, %3;" : "=l"(d) : "l"(a), "l"(b), "l"(c));
    return d;
}

// ---------- GEMM tile constants (64 points x 256 co per block) ----------
constexpr int TPTS = 64;
constexpr int SM_FSM = 0;        // 16384 floats
constexpr int SM_WSM = 16384;    // 2048 floats (single buffer)
constexpr int SM_W2  = 18432;    // 768
constexpr int SM_B2  = 19200;    // 4
constexpr int SM1_FLOATS = 19204;
constexpr int SM_VSM = 19204;    // 900
constexpr int SM_IDX = 20104;    // 64 ints
constexpr int SM_VPS = 20168;    // 192
constexpr int SM4_FLOATS = 20360;

// tx=tid&7 owns pts 8tx..8tx+7, ty=tid>>3 owns co 8ty..8ty+7. (round-6 version: 128 regs)
__device__ __forceinline__ void gemm_tile(const float* __restrict__ W, float* sm,
                                          int tid, int tx, int ty, float acc[8][8]) {
    float* fsm = sm + SM_FSM;
    float* wsm = sm + SM_WSM;
    unsigned long long acc2[8][4];
#pragma unroll
    for (int j = 0; j < 8; ++j)
#pragma unroll
        for (int q = 0; q < 4; ++q) acc2[j][q] = 0ull;

    for (int ck = 0; ck < 32; ++ck) {
        {
            const float4* srcw = reinterpret_cast<const float4*>(W + tid * 256 + ck * 8);
            float4 a = srcw[0], b = srcw[1];
            wsm[0 * 256 + tid] = a.x; wsm[1 * 256 + tid] = a.y;
            wsm[2 * 256 + tid] = a.z; wsm[3 * 256 + tid] = a.w;
            wsm[4 * 256 + tid] = b.x; wsm[5 * 256 + tid] = b.y;
            wsm[6 * 256 + tid] = b.z; wsm[7 * 256 + tid] = b.w;
        }
        __syncthreads();
#pragma unroll
        for (int ci = 0; ci < 8; ++ci) {
            const float* wrow = wsm + ci * 256 + 8 * ty;
            float4 wa = *reinterpret_cast<const float4*>(wrow);
            float4 wb = *reinterpret_cast<const float4*>(wrow + 4);
            const float* frow = fsm + (ck * 8 + ci) * TPTS + 8 * tx;
            float4 fa = *reinterpret_cast<const float4*>(frow);
            float4 fb = *reinterpret_cast<const float4*>(frow + 4);
            unsigned long long f2[4] = {pk2(fa.x, fa.y), pk2(fa.z, fa.w),
                                        pk2(fb.x, fb.y), pk2(fb.z, fb.w)};
            float w[8] = {wa.x, wa.y, wa.z, wa.w, wb.x, wb.y, wb.z, wb.w};
#pragma unroll
            for (int j = 0; j < 8; ++j) {
                unsigned long long wd = pk2(w[j], w[j]);
#pragma unroll
                for (int q = 0; q < 4; ++q) acc2[j][q] = fma2(f2[q], wd, acc2[j][q]);
            }
        }
        __syncthreads();
    }
#pragma unroll
    for (int j = 0; j < 8; ++j)
#pragma unroll
        for (int q = 0; q < 4; ++q) up2(acc2[j][q], acc[j][2 * q], acc[j][2 * q + 1]);
}

__device__ __forceinline__ void bn_params(const float* gg, const float* be, const float* mm,
                                          const float* vv, const float* b1, int ty,
                                          float sc[8], float bias2[8], float b1v[8]) {
#pragma unroll
    for (int j = 0; j < 8; ++j) {
        int co = 8 * ty + j;
        float s = __fdiv_rn(gg[co], sqrtf(__fadd_rn(vv[co], 1e-5f)));
        sc[j] = s;
        bias2[j] = __fsub_rn(be[co], __fmul_rn(mm[co], s));
        b1v[j] = b1[co];
    }
}

__device__ __forceinline__ void head3(const float* w2sm, float acc[8][8],
                                      const float sc[8], const float bias2[8],
                                      const float b1v[8], int ty, float p3[3][8]) {
#pragma unroll
    for (int j = 0; j < 8; ++j) {
        int co = 8 * ty + j;
        float w0 = w2sm[co], w1c = w2sm[256 + co], w2c = w2sm[512 + co];
#pragma unroll
        for (int p = 0; p < 8; ++p) {
            float t = __fadd_rn(acc[j][p], b1v[j]);
            t = __fmul_rn(t, sc[j]);
            t = __fadd_rn(t, bias2[j]);
            float h = fmaxf(t, 0.f);
            p3[0][p] = fmaf(w0, h, p3[0][p]);
            p3[1][p] = fmaf(w1c, h, p3[1][p]);
            p3[2][p] = fmaf(w2c, h, p3[2][p]);
        }
    }
}

__device__ __forceinline__ void reduce3(float* red, float p3[3][8], int tx, int ty) {
#pragma unroll
    for (int k = 0; k < 3; ++k)
#pragma unroll
        for (int p = 0; p < 8; ++p) red[ty * 192 + k * 64 + 8 * tx + p] = p3[k][p];
    __syncthreads();
    for (int s = 16; s >= 1; s >>= 1) {
        if (ty < s) {
#pragma unroll
            for (int k = 0; k < 3; ++k)
#pragma unroll
                for (int p = 0; p < 8; ++p)
                    red[ty * 192 + k * 64 + 8 * tx + p] +=
                        red[(ty + s) * 192 + k * 64 + 8 * tx + p];
        }
        __syncthreads();
    }
}

// ================= K1 =================
__global__ __launch_bounds__(256) void k_gemm_mask(
    const float* __restrict__ F, const float* __restrict__ W1, const float* __restrict__ b1,
    const float* __restrict__ gg, const float* __restrict__ be, const float* __restrict__ mm,
    const float* __restrict__ vv, const float* __restrict__ W2, const float* __restrict__ b2,
    float* __restrict__ out) {
    extern __shared__ float sm[];
    float* fsm  = sm + SM_FSM;
    float* w2sm = sm + SM_W2;
    float* b2sm = sm + SM_B2;

    int b = blockIdx.y, n0 = blockIdx.x * TPTS, tid = threadIdx.x;
    int tx = tid & 7, ty = tid >> 3;

    for (int t = tid; t < 768; t += 256) w2sm[t] = W2[t];
    if (tid < 3) b2sm[tid] = b2[tid];

    float sc[8], bias2[8], b1v[8];
    bn_params(gg, be, mm, vv, b1, ty, sc, bias2, b1v);

    const float* Fb = F + (size_t)b * Cc * Np;
    for (int idx = tid; idx < 256 * TPTS; idx += 256) {
        int c = idx >> 6, p = idx & 63;
        int n = n0 + p;
        fsm[idx] = (n < Np) ? Fb[(size_t)c * Np + n] : 0.f;
    }
    __syncthreads();

    float acc[8][8];
    gemm_tile(W1, sm, tid, tx, ty, acc);

    float p3[3][8];
#pragma unroll
    for (int k = 0; k < 3; ++k)
#pragma unroll
        for (int p = 0; p < 8; ++p) p3[k][p] = 0.f;
    head3(w2sm, acc, sc, bias2, b1v, ty, p3);

    float* red = fsm;
    reduce3(red, p3, tx, ty);

    if (ty == 0) {
#pragma unroll
        for (int p = 0; p < 8; ++p) {
            int pt = 8 * tx + p;
            int n = n0 + pt;
            if (n < Np) {
                float s0 = __fadd_rn(red[pt], b2sm[0]);
                float s1 = __fadd_rn(red[64 + pt], b2sm[1]);
                float gr = __fadd_rn(red[128 + pt], b2sm[2]);
                out[OFF0 + (size_t)b * 2 * Np + n] = s0;
                out[OFF0 + (size_t)b * 2 * Np + Np + n] = s1;
                out[OFF1 + (size_t)b * Np + n] = gr;
                g_mask[b * Np + n] = (unsigned char)((s1 > s0) && (gr > 0.1f));
            }
        }
    }
}

// ================= K3: reg-xyz + redux-reduce masked FPS =================
constexpr int SMPTS = 10240;     // xyz slots in smem
constexpr int RXYZ  = 5;         // xyz register slots (first 5120 points)
constexpr int RSLOT = 10;        // dist register slots (first 10240 points)
// smem byte offsets
constexpr int FP_SXYZ   = 0;         // 163840
constexpr int FP_SEQ    = 163840;    // 4096
constexpr int FP_REDD   = 167936;    // 2x32 u32 = 256
constexpr int FP_REDI   = 168192;    // 2x32 s32 = 256
constexpr int FP_WCNT   = 168448;    // 128
constexpr int FP_SBASE  = 168576;    // 64 (pad)
constexpr int FP_DISTOV = 168640;    // (Np-SMPTS)*4 = 39040
constexpr int FP_BYTES  = 207680;

__global__ __launch_bounds__(1024, 1) void k_fps(const float* __restrict__ xyz,
                                                 float* __restrict__ out) {
    extern __shared__ char smc[];
    float4* sxyz  = (float4*)(smc + FP_SXYZ);
    int*    seq   = (int*)(smc + FP_SEQ);
    unsigned* redD = (unsigned*)(smc + FP_REDD);
    int*    redI  = (int*)(smc + FP_REDI);
    int*    wcnt  = (int*)(smc + FP_WCNT);
    int*    sBase = (int*)(smc + FP_SBASE);
    float*  distOv= (float*)(smc + FP_DISTOV);

    int b = blockIdx.x, tid = threadIdx.x, lane = tid & 31, wid = tid >> 5;
    const float* xb = xyz + (size_t)b * Np * 3;

    if (tid == 0) sBase[0] = 0;
    __syncthreads();

    // stable stream compaction of masked points
    for (int c0 = 0; c0 < Np; c0 += 1024) {
        int n = c0 + tid;
        bool mk = (n < Np) && g_mask[b * Np + n];
        unsigned bal = __ballot_sync(0xffffffffu, mk);
        int pre = __popc(bal & ((1u << lane) - 1u));
        if (lane == 0) wcnt[wid] = __popc(bal);
        __syncthreads();
        if (tid == 0) {
            int a = sBase[0];
            for (int w = 0; w < 32; ++w) { int t = wcnt[w]; wcnt[w] = a; a += t; }
            sBase[0] = a;
        }
        __syncthreads();
        if (mk) {
            int pos = wcnt[wid] + pre;
            float4 p = make_float4(xb[n * 3], xb[n * 3 + 1], xb[n * 3 + 2], 0.f);
            g_cidx[b][pos] = n;
            g_cxyz[b][pos] = p;
            if (pos < SMPTS) sxyz[pos] = p;
        }
        __syncthreads();
    }
    int M = sBase[0];
    const float NEGINF = __int_as_float(0xff800000);

    float rd[RSLOT];
#pragma unroll
    for (int k = 0; k < RSLOT; ++k)
        rd[k] = (k * 1024 + tid < M) ? 1e10f : NEGINF;
    float rx[RXYZ], ry[RXYZ], rz[RXYZ];
#pragma unroll
    for (int k = 0; k < RXYZ; ++k) {   // stale reads beyond M are guarded by rd=NEGINF
        float4 p = sxyz[k * 1024 + tid];
        rx[k] = p.x; ry[k] = p.y; rz[k] = p.z;
    }
    for (int i = tid; i < M - SMPTS; i += 1024) distOv[i] = 1e10f;
    if (tid == 0) seq[0] = 0;
    __syncthreads();

    if (M > 0) {
        float4 p0 = sxyz[0];
        float px = p0.x, py = p0.y, pz = p0.z;
        for (int s = 1; s < NS; ++s) {
            float best = NEGINF;
            int bi = 0x7fffffff;
#pragma unroll
            for (int k = 0; k < RXYZ; ++k) {
                if (k * 1024 < M) {  // uniform branch
                    float dx = __fsub_rn(rx[k], px);
                    float dy = __fsub_rn(ry[k], py);
                    float dz = __fsub_rn(rz[k], pz);
                    float d = __fadd_rn(__fadd_rn(__fmul_rn(dx, dx), __fmul_rn(dy, dy)),
                                        __fmul_rn(dz, dz));
                    float nd = fminf(rd[k], d);
                    rd[k] = nd;
                    if (nd > best) { best = nd; bi = k * 1024 + tid; }
                }
            }
#pragma unroll
            for (int k = RXYZ; k < RSLOT; ++k) {
                if (k * 1024 < M) {
                    float4 p = sxyz[k * 1024 + tid];
                    float dx = __fsub_rn(p.x, px);
                    float dy = __fsub_rn(p.y, py);
                    float dz = __fsub_rn(p.z, pz);
                    float d = __fadd_rn(__fadd_rn(__fmul_rn(dx, dx), __fmul_rn(dy, dy)),
                                        __fmul_rn(dz, dz));
                    float nd = fminf(rd[k], d);
                    rd[k] = nd;
                    if (nd > best) { best = nd; bi = k * 1024 + tid; }
                }
            }
            for (int i = SMPTS + tid; i < M; i += 1024) {  // overflow (rare)
                float4 p = g_cxyz[b][i];
                float dx = __fsub_rn(p.x, px);
                float dy = __fsub_rn(p.y, py);
                float dz = __fsub_rn(p.z, pz);
                float d = __fadd_rn(__fadd_rn(__fmul_rn(dx, dx), __fmul_rn(dy, dy)),
                                    __fmul_rn(dz, dz));
                float nd = fminf(distOv[i - SMPTS], d);
                distOv[i - SMPTS] = nd;
                if (nd > best) { best = nd; bi = i; }
            }
            // REDUX two-level argmax: dist-bits max (u32, dists >= 0), ties -> min idx
            unsigned db = (bi == 0x7fffffff) ? 0u : __float_as_uint(best);
            unsigned mx = __reduce_max_sync(0xffffffffu, db);
            int cand = (db == mx) ? bi : 0x7fffffff;
            int wmin = __reduce_min_sync(0xffffffffu, cand);
            int buf = (s & 1) * 32;
            if (lane == 0) { redD[buf + wid] = mx; redI[buf + wid] = wmin; }
            __syncthreads();
            unsigned db2 = redD[buf + lane];
            int bi2 = redI[buf + lane];
            unsigned mx2 = __reduce_max_sync(0xffffffffu, db2);
            int cand2 = (db2 == mx2) ? bi2 : 0x7fffffff;
            int win = __reduce_min_sync(0xffffffffu, cand2);
            if (tid == 0) seq[s] = win;
            float4 pw = (win < SMPTS) ? sxyz[win] : g_cxyz[b][win];
            px = pw.x; py = pw.y; pz = pw.z;
        }
    }
    __syncthreads();

    // epilogue: inds / xyz / fp2_graspness
    {
        int orig; float x, y, z;
        if (M > 0) {
            int c = seq[tid];
            orig = g_cidx[b][c];
            float4 p = g_cxyz[b][c];
            x = p.x; y = p.y; z = p.z;
        } else {
            orig = 0; x = xb[0]; y = xb[1]; z = xb[2];
        }
        out[OFF3 + (size_t)b * NS + tid] = (float)orig;
        out[OFF2 + (size_t)b * NS * 3 + tid * 3 + 0] = x;
        out[OFF2 + (size_t)b * NS * 3 + tid * 3 + 1] = y;
        out[OFF2 + (size_t)b * NS * 3 + tid * 3 + 2] = z;
        out[OFF5 + (size_t)b * NS + tid] = out[OFF1 + (size_t)b * Np + orig];
        g_sel[b][tid] = orig;
    }
}

// ================= K4 =================
__global__ __launch_bounds__(256) void k_view(
    const float* __restrict__ F, const float* __restrict__ W1, const float* __restrict__ b1,
    const float* __restrict__ gg, const float* __restrict__ be, const float* __restrict__ mm,
    const float* __restrict__ vv, const float* __restrict__ W2, const float* __restrict__ b2,
    float* __restrict__ out) {
    extern __shared__ float sm[];
    float* fsm  = sm + SM_FSM;
    float* w2sm = sm + SM_W2;
    float* b2sm = sm + SM_B2;
    float* vsm  = sm + SM_VSM;
    int*   idxs = (int*)(sm + SM_IDX);
    float* vps  = sm + SM_VPS;

    int b = blockIdx.y, s0 = blockIdx.x * TPTS, tid = threadIdx.x;
    int tx = tid & 7, ty = tid >> 3;

    if (tid < TPTS) idxs[tid] = g_sel[b][s0 + tid];
    for (int t = tid; t < 768; t += 256) w2sm[t] = W2[t];
    if (tid < 3) b2sm[tid] = b2[tid];

    for (int i = tid; i < NV; i += 256) {
        double z = (2.0 * (double)i + 1.0) / (double)NV - 1.0;
        double r = sqrt(fmax(1.0 - z * z, 0.0));
        double phi = (sqrt(5.0) - 1.0) / 2.0;
        double ang = (2.0 * 3.14159265358979323846) * (double)i * phi;
        float x = (float)(r * cos(ang)), y = (float)(r * sin(ang)), zf = (float)z;
        float nr2 = __fadd_rn(__fadd_rn(__fmul_rn(x, x), __fmul_rn(y, y)), __fmul_rn(zf, zf));
        float nr = fmaxf(sqrtf(nr2), 1e-8f);
        vsm[i * 3 + 0] = __fdiv_rn(x, nr);
        vsm[i * 3 + 1] = __fdiv_rn(y, nr);
        vsm[i * 3 + 2] = __fdiv_rn(zf, nr);
    }

    float sc[8], bias2[8], b1v[8];
    bn_params(gg, be, mm, vv, b1, ty, sc, bias2, b1v);
    __syncthreads();

    const float* Fb = F + (size_t)b * Cc * Np;
    for (int idx = tid; idx < 256 * TPTS; idx += 256) {
        int c = idx >> 6, s = idx & 63;
        float val = Fb[(size_t)c * Np + idxs[s]];
        fsm[idx] = val;
        out[OFF4 + (size_t)b * Cc * NS + (size_t)c * NS + s0 + s] = val;
    }
    __syncthreads();

    float acc[8][8];
    gemm_tile(W1, sm, tid, tx, ty, acc);

    float p3[3][8];
#pragma unroll
    for (int k = 0; k < 3; ++k)
#pragma unroll
        for (int p = 0; p < 8; ++p) p3[k][p] = 0.f;
    head3(w2sm, acc, sc, bias2, b1v, ty, p3);

    float* red = fsm;
    reduce3(red, p3, tx, ty);

    if (ty == 0) {
#pragma unroll
        for (int p = 0; p < 8; ++p) {
            int pt = 8 * tx + p;
            int s = s0 + pt;
            float v0 = __fadd_rn(red[pt], b2sm[0]);
            float v1 = __fadd_rn(red[64 + pt], b2sm[1]);
            float v2 = __fadd_rn(red[128 + pt], b2sm[2]);
            out[OFF6 + (size_t)b * NS * 3 + (size_t)s * 3 + 0] = v0;
            out[OFF6 + (size_t)b * NS * 3 + (size_t)s * 3 + 1] = v1;
            out[OFF6 + (size_t)b * NS * 3 + (size_t)s * 3 + 2] = v2;
            vps[pt * 3 + 0] = v0; vps[pt * 3 + 1] = v1; vps[pt * 3 + 2] = v2;
        }
    }
    __syncthreads();

    if (tid < TPTS) {
        int s = s0 + tid;
        float vx = vps[tid * 3], vy = vps[tid * 3 + 1], vz = vps[tid * 3 + 2];
        float n2 = __fadd_rn(__fadd_rn(__fmul_rn(vx, vx), __fmul_rn(vy, vy)), __fmul_rn(vz, vz));
        float nr = fmaxf(sqrtf(n2), 1e-8f);
        float ax_ = __fdiv_rn(vx, nr), ay_ = __fdiv_rn(vy, nr), az_ = __fdiv_rn(vz, nr);
        float best = __int_as_float(0xff800000);
        int bi = 0;
        for (int v = 0; v < NV; ++v) {
            float c = __fadd_rn(__fadd_rn(__fmul_rn(ax_, vsm[v * 3]),
                                          __fmul_rn(ay_, vsm[v * 3 + 1])),
                                __fmul_rn(az_, vsm[v * 3 + 2]));
            if (c > best) { best = c; bi = v; }
        }
        out[OFF7 + (size_t)b * NS + s] = (float)bi;

        float tx0 = -vx, tx1 = -vy, tx2 = -vz;
        float ay0 = -tx1, ay1 = tx0, ay2 = 0.f;
        float s2 = ay0 * ay0 + ay1 * ay1;
        if (s2 == 0.f) { ay0 = 0.f; ay1 = 1.f; ay2 = 0.f; }
        float an = sqrtf(tx0 * tx0 + tx1 * tx1 + tx2 * tx2);
        float nx0 = tx0 / an, nx1 = tx1 / an, nx2 = tx2 / an;
        float bn = sqrtf(ay0 * ay0 + ay1 * ay1 + ay2 * ay2);
        float ny0 = ay0 / bn, ny1 = ay1 / bn, ny2 = ay2 / bn;
        float nz0 = nx1 * ny2 - nx2 * ny1;
        float nz1 = nx2 * ny0 - nx0 * ny2;
        float nz2 = nx0 * ny1 - nx1 * ny0;
        size_t base = OFF8 + ((size_t)b * NS + s) * 9;
        out[base + 0] = nx0; out[base + 1] = ny0; out[base + 2] = nz0;
        out[base + 3] = nx1; out[base + 4] = ny1; out[base + 5] = nz1;
        out[base + 6] = nx2; out[base + 7] = ny2; out[base + 8] = nz2;
    }
}

// ================= launch (robust input-order detection) =================
extern "C" void kernel_launch(void* const* d_in, const int* in_sizes, int n_in,
                              void* d_out, int out_size) {
    const float *xyz, *F, *w1, *b1, *gg, *be, *mm, *vv, *w2, *b2;
    const float *c1w, *c1b, *bng, *bnb, *bnm, *bnv, *c2w, *c2b;

    int imax = 0;
    for (int i = 1; i < n_in; ++i)
        if (in_sizes[i] > in_sizes[imax]) imax = i;

    if (imax == 1) {  // dict-insertion / signature order
        xyz = (const float*)d_in[0];  F   = (const float*)d_in[1];
        w1  = (const float*)d_in[2];  b1  = (const float*)d_in[3];
        gg  = (const float*)d_in[4];  be  = (const float*)d_in[5];
        mm  = (const float*)d_in[6];  vv  = (const float*)d_in[7];
        w2  = (const float*)d_in[8];  b2  = (const float*)d_in[9];
        c1w = (const float*)d_in[10]; c1b = (const float*)d_in[11];
        bng = (const float*)d_in[12]; bnb = (const float*)d_in[13];
        bnm = (const float*)d_in[14]; bnv = (const float*)d_in[15];
        c2w = (const float*)d_in[16]; c2b = (const float*)d_in[17];
    } else {          // alphabetical order
        bnb = (const float*)d_in[0];  bng = (const float*)d_in[1];
        bnm = (const float*)d_in[2];  bnv = (const float*)d_in[3];
        c1b = (const float*)d_in[4];  c1w = (const float*)d_in[5];
        c2b = (const float*)d_in[6];  c2w = (const float*)d_in[7];
        b1  = (const float*)d_in[8];  b2  = (const float*)d_in[9];
        be  = (const float*)d_in[10]; gg  = (const float*)d_in[11];
        mm  = (const float*)d_in[12]; vv  = (const float*)d_in[13];
        w1  = (const float*)d_in[14]; w2  = (const float*)d_in[15];
        F   = (const float*)d_in[16]; xyz = (const float*)d_in[17];
    }
    float* out = (float*)d_out;

    const int SM1 = SM1_FLOATS * 4;
    const int SM3 = FP_BYTES;
    const int SM4 = SM4_FLOATS * 4;
    cudaFuncSetAttribute(k_gemm_mask, cudaFuncAttributeMaxDynamicSharedMemorySize, SM1);
    cudaFuncSetAttribute(k_fps, cudaFuncAttributeMaxDynamicSharedMemorySize, SM3);
    cudaFuncSetAttribute(k_view, cudaFuncAttributeMaxDynamicSharedMemorySize, SM4);

    dim3 g1((Np + TPTS - 1) / TPTS, Bb);
    k_gemm_mask<<<g1, 256, SM1>>>(F, w1, b1, gg, be, mm, vv, w2, b2, out);
    k_fps<<<Bb, 1024, SM3>>>(xyz, out);
    dim3 g4(NS / TPTS, Bb);
    k_view<<<g4, 256, SM4>>>(F, c1w, c1b, bng, bnb, bnm, bnv, c2w, c2b, out);
}